// round 1
// baseline (speedup 1.0000x reference)
#include <cuda_runtime.h>

// NCM_1846835937566: 32-node neural causal model, B=32768.
// Fused single-kernel: each thread owns one sample end-to-end; nodes processed
// sequentially (true data dependency via thresholded parents); weights staged
// per-node into SMEM; fp32 math via packed fma.rn.f32x2 (FFMA2).

#define NNODES 32
#define ENDO   16
#define EXO    16
#define HID    64
#define TPB    128
#define BATCH  32768
#define NBLK   (BATCH / TPB)   // 256

typedef unsigned long long u64;
typedef unsigned int       u32;

__device__ __forceinline__ u64 fma2(u64 a, u64 b, u64 c) {
    u64 d;
    asm("fma.rn.f32x2 %0, %1, %2, %3;" : "=l"(d) : "l"(a), "l"(b), "l"(c));
    return d;
}
__device__ __forceinline__ u64 dup2(float x) {
    u64 d;
    asm("mov.b64 %0, {%1, %1};" : "=l"(d) : "f"(x));
    return d;
}
__device__ __forceinline__ void unpk(u64 a, float& lo, float& hi) {
    asm("mov.b64 {%0, %1}, %2;" : "=f"(lo), "=f"(hi) : "l"(a));
}

// SMEM layout (floats)
#define OFF_W1 0                       // 80*64  = 5120
#define OFF_W2 (OFF_W1 + 80 * 64)      // 64*64  = 4096
#define OFF_W3 (OFF_W2 + 64 * 64)      // 64*16  = 1024
#define OFF_B1 (OFF_W3 + 64 * 16)      // 64
#define OFF_B2 (OFF_B1 + 64)           // 64
#define OFF_B3 (OFF_B2 + 64)           // 16
#define OFF_U  (OFF_B3 + 16)           // 16*TPB = 2048
#define OFF_H  (OFF_U + EXO * TPB)     // 64*TPB = 8192
#define SMEM_FLOATS (OFF_H + HID * TPB)
#define SMEM_BYTES  (SMEM_FLOATS * 4)  // 82496

__global__ __launch_bounds__(TPB) void ncm_kernel(
    const float* __restrict__ u,
    const float* __restrict__ w_r1, const float* __restrict__ b_r1,
    const float* __restrict__ w_r2, const float* __restrict__ b_r2,
    const float* __restrict__ w_r3, const float* __restrict__ b_r3,
    const float* __restrict__ w_i1, const float* __restrict__ b_i1,
    const float* __restrict__ w_i2, const float* __restrict__ b_i2,
    const float* __restrict__ w_i3, const float* __restrict__ b_i3,
    float* __restrict__ out)
{
    extern __shared__ float smem[];
    float* s_w1 = smem + OFF_W1;
    float* s_w2 = smem + OFF_W2;
    float* s_w3 = smem + OFF_W3;
    float* s_b1 = smem + OFF_B1;
    float* s_b2 = smem + OFF_B2;
    float* s_b3 = smem + OFF_B3;
    float* s_u  = smem + OFF_U;
    float* s_h  = smem + OFF_H;

    const int tid = threadIdx.x;
    const int b   = blockIdx.x * TPB + tid;

    // Rolling 64-bit parent window: bits [16p .. 16p+15] = node (i-4+p),
    // i.e. exactly the concat order the reference uses.
    u64 pm = 0ull;

    for (int node = 0; node < NNODES; ++node) {
        const bool root = (node < 4);
        const int IN = root ? EXO : (64 + EXO);

        const float *g1, *g2, *g3, *gb1, *gb2, *gb3;
        if (root) {
            g1 = w_r1 + node * (EXO * HID);
            g2 = w_r2 + node * (HID * HID);
            g3 = w_r3 + node * (HID * ENDO);
            gb1 = b_r1 + node * HID;
            gb2 = b_r2 + node * HID;
            gb3 = b_r3 + node * ENDO;
        } else {
            const int j = node - 4;
            g1 = w_i1 + j * (80 * HID);
            g2 = w_i2 + j * (HID * HID);
            g3 = w_i3 + j * (HID * ENDO);
            gb1 = b_i1 + j * HID;
            gb2 = b_i2 + j * HID;
            gb3 = b_i3 + j * ENDO;
        }

        __syncthreads();  // previous iteration's SMEM reads done

        // ---- stage weights + biases + this node's u-slice into SMEM ----
        {
            const int n1 = (IN * HID) / 4;
            for (int i = tid; i < n1; i += TPB)
                ((float4*)s_w1)[i] = ((const float4*)g1)[i];
            for (int i = tid; i < (HID * HID) / 4; i += TPB)
                ((float4*)s_w2)[i] = ((const float4*)g2)[i];
            for (int i = tid; i < (HID * ENDO) / 4; i += TPB)
                ((float4*)s_w3)[i] = ((const float4*)g3)[i];
            if (tid < HID) { s_b1[tid] = gb1[tid]; s_b2[tid] = gb2[tid]; }
            if (tid < ENDO) s_b3[tid] = gb3[tid];
            // u tile transposed: s_u[k][sample] for conflict-free per-thread reads
            for (int i = tid; i < EXO * TPB; i += TPB) {
                const int s = i >> 4, k = i & 15;
                s_u[k * TPB + s] =
                    u[(size_t)(blockIdx.x * TPB + s) * (NNODES * EXO) + node * EXO + k];
            }
        }
        __syncthreads();

        u64 acc[32];

        // ---- layer 1: IN -> 64 ----
        #pragma unroll
        for (int o = 0; o < 32; ++o) acc[o] = ((const u64*)s_b1)[o];

        if (!root) {
            // 64 binary parent features (exact in fp32)
            #pragma unroll 2
            for (int k = 0; k < 64; ++k) {
                const float x = (float)((pm >> k) & 1ull);
                const u64 xd = dup2(x);
                const u64* wr = (const u64*)(s_w1 + (k << 6));
                #pragma unroll
                for (int o = 0; o < 32; ++o) acc[o] = fma2(wr[o], xd, acc[o]);
            }
        }
        const int uoff = root ? 0 : 64;
        #pragma unroll 2
        for (int d = 0; d < EXO; ++d) {
            const u64 xd = dup2(s_u[d * TPB + tid]);
            const u64* wr = (const u64*)(s_w1 + ((uoff + d) << 6));
            #pragma unroll
            for (int o = 0; o < 32; ++o) acc[o] = fma2(wr[o], xd, acc[o]);
        }
        // relu -> s_h
        #pragma unroll
        for (int o = 0; o < 32; ++o) {
            float lo, hi; unpk(acc[o], lo, hi);
            s_h[(2 * o) * TPB + tid]     = fmaxf(lo, 0.0f);
            s_h[(2 * o + 1) * TPB + tid] = fmaxf(hi, 0.0f);
        }

        // ---- layer 2: 64 -> 64 ----
        #pragma unroll
        for (int o = 0; o < 32; ++o) acc[o] = ((const u64*)s_b2)[o];
        #pragma unroll 2
        for (int k = 0; k < 64; ++k) {
            const u64 xd = dup2(s_h[k * TPB + tid]);
            const u64* wr = (const u64*)(s_w2 + (k << 6));
            #pragma unroll
            for (int o = 0; o < 32; ++o) acc[o] = fma2(wr[o], xd, acc[o]);
        }
        #pragma unroll
        for (int o = 0; o < 32; ++o) {
            float lo, hi; unpk(acc[o], lo, hi);
            s_h[(2 * o) * TPB + tid]     = fmaxf(lo, 0.0f);
            s_h[(2 * o + 1) * TPB + tid] = fmaxf(hi, 0.0f);
        }

        // ---- layer 3: 64 -> 16 (no relu) ----
        u64 acc3[8];
        #pragma unroll
        for (int o = 0; o < 8; ++o) acc3[o] = ((const u64*)s_b3)[o];
        #pragma unroll 2
        for (int k = 0; k < 64; ++k) {
            const u64 xd = dup2(s_h[k * TPB + tid]);
            const u64* wr = (const u64*)(s_w3 + (k << 4));
            #pragma unroll
            for (int o = 0; o < 8; ++o) acc3[o] = fma2(wr[o], xd, acc3[o]);
        }

        float v[16];
        #pragma unroll
        for (int o = 0; o < 8; ++o) unpk(acc3[o], v[2 * o], v[2 * o + 1]);

        // threshold -> next window bits
        u32 nb = 0;
        #pragma unroll
        for (int d = 0; d < 16; ++d) nb |= (v[d] > 0.5f) ? (1u << d) : 0u;
        pm = (pm >> 16) | ((u64)nb << 48);

        // store logits (out[b, node*16 .. +15]) — 4x vec4, fully-written sectors
        float4* o4 = (float4*)(out + (size_t)b * (NNODES * ENDO) + node * ENDO);
        #pragma unroll
        for (int q = 0; q < 4; ++q)
            o4[q] = make_float4(v[4 * q], v[4 * q + 1], v[4 * q + 2], v[4 * q + 3]);
    }
}

extern "C" void kernel_launch(void* const* d_in, const int* in_sizes, int n_in,
                              void* d_out, int out_size) {
    (void)in_sizes; (void)n_in; (void)out_size;
    cudaFuncSetAttribute(ncm_kernel, cudaFuncAttributeMaxDynamicSharedMemorySize,
                         SMEM_BYTES);
    ncm_kernel<<<NBLK, TPB, SMEM_BYTES>>>(
        (const float*)d_in[0],
        (const float*)d_in[1], (const float*)d_in[2],
        (const float*)d_in[3], (const float*)d_in[4],
        (const float*)d_in[5], (const float*)d_in[6],
        (const float*)d_in[7], (const float*)d_in[8],
        (const float*)d_in[9], (const float*)d_in[10],
        (const float*)d_in[11], (const float*)d_in[12],
        (float*)d_out);
}

// round 2
// speedup vs baseline: 1.3836x; 1.3836x over previous
#include <cuda_runtime.h>

// NCM_1846835937566 R2: warp-tile restructure.
// Warp = 32 samples (16 f32x2 sample-pairs); lane owns 2 output columns.
// Weights: 1 coalesced LDS.64 per lane per k (amortized over 16 sample-pairs).
// Activations: per-warp SMEM in pair-layout [pair][k] (u64), loaded as LDS.128
// broadcast for 2 k's at once. Parent bits: 4-slot ring of 0/1 float rows.

#define TPB   256
#define NBLK  128
#define NNODES 32

typedef unsigned long long u64;
typedef unsigned int u32;

__device__ __forceinline__ u64 fma2(u64 a, u64 b, u64 c) {
    u64 d; asm("fma.rn.f32x2 %0,%1,%2,%3;" : "=l"(d) : "l"(a), "l"(b), "l"(c));
    return d;
}
__device__ __forceinline__ u64 dup2(float x) {
    u64 d; asm("mov.b64 %0,{%1,%1};" : "=l"(d) : "f"(x)); return d;
}
__device__ __forceinline__ void unpk(u64 a, float& lo, float& hi) {
    asm("mov.b64 {%0,%1},%2;" : "=f"(lo), "=f"(hi) : "l"(a));
}
__device__ __forceinline__ u64 pk(float lo, float hi) {
    u64 d; asm("mov.b64 %0,{%1,%2};" : "=l"(d) : "f"(lo), "f"(hi)); return d;
}
__device__ __forceinline__ u64 relu2(u64 a) {
    float lo, hi; unpk(a, lo, hi);
    return pk(fmaxf(lo, 0.0f), fmaxf(hi, 0.0f));
}

// SMEM float region: w1[80][64] | w2[64][64] | w3[64][16] | b1[64] b2[64] b3[16]
#define OFF_W2 5120
#define OFF_W3 9216
#define OFF_B1 10240
#define OFF_B2 10304
#define OFF_B3 10368
#define WOFF_FLOATS 10384               // 41536 bytes, 8B-aligned

// per-warp u64 region: in_pair[16][IN_STR] (rows 0..63 = parent ring, 64..79 = u)
//                      h_pair[16][H_STR]
#define IN_STR 82
#define H_STR  66
#define IN_PER_WARP (16 * IN_STR)       // 1312 u64
#define H_PER_WARP  (16 * H_STR)        // 1056 u64
#define WARP_U64 (IN_PER_WARP + H_PER_WARP)
#define SMEM_BYTES (WOFF_FLOATS * 4 + 8 * WARP_U64 * 8)   // 193088

__global__ void __launch_bounds__(TPB, 1) ncm_kernel(
    const float* __restrict__ u,
    const float* __restrict__ w_r1, const float* __restrict__ b_r1,
    const float* __restrict__ w_r2, const float* __restrict__ b_r2,
    const float* __restrict__ w_r3, const float* __restrict__ b_r3,
    const float* __restrict__ w_i1, const float* __restrict__ b_i1,
    const float* __restrict__ w_i2, const float* __restrict__ b_i2,
    const float* __restrict__ w_i3, const float* __restrict__ b_i3,
    float* __restrict__ out)
{
    extern __shared__ float smem[];
    float* s_w1 = smem;
    float* s_w2 = smem + OFF_W2;
    float* s_w3 = smem + OFF_W3;
    float* s_b1 = smem + OFF_B1;
    float* s_b2 = smem + OFF_B2;
    float* s_b3 = smem + OFF_B3;
    u64* pair_base = (u64*)(smem + WOFF_FLOATS);

    const int tid = threadIdx.x;
    const int wp = tid >> 5, l = tid & 31;
    u64* s_in = pair_base + wp * WARP_U64;                 // [16][IN_STR]
    u64* s_h  = pair_base + wp * WARP_U64 + IN_PER_WARP;   // [16][H_STR]

    const int q8 = l & 7;      // layer3: output-pair index (outputs 2q8, 2q8+1)
    const int g  = l >> 3;     // layer3: sample-pair group (pairs 4g..4g+3)
    const long sbase = (long)blockIdx.x * TPB + wp * 32;

    u64 acc0[16], acc1[16];

    for (int node = 0; node < NNODES; ++node) {
        const bool root = (node < 4);
        const float *g1, *g2, *g3, *gb1, *gb2, *gb3;
        if (root) {
            g1 = w_r1 + node * (16 * 64);
            g2 = w_r2 + node * (64 * 64);
            g3 = w_r3 + node * (64 * 16);
            gb1 = b_r1 + node * 64; gb2 = b_r2 + node * 64; gb3 = b_r3 + node * 16;
        } else {
            const int j = node - 4;
            g1 = w_i1 + j * (80 * 64);
            g2 = w_i2 + j * (64 * 64);
            g3 = w_i3 + j * (64 * 16);
            gb1 = b_i1 + j * 64; gb2 = b_i2 + j * 64; gb3 = b_i3 + j * 16;
        }

        __syncthreads();  // all warps done reading previous node's weights

        // ---- stage weights (CTA-wide, coalesced float4) ----
        {
            const int n1 = root ? (16 * 64 / 4) : (80 * 64 / 4);
            for (int i = tid; i < n1; i += TPB)
                ((float4*)s_w1)[i] = ((const float4*)g1)[i];
            for (int i = tid; i < 64 * 64 / 4; i += TPB)
                ((float4*)s_w2)[i] = ((const float4*)g2)[i];
            for (int i = tid; i < 64 * 16 / 4; i += TPB)
                ((float4*)s_w3)[i] = ((const float4*)g3)[i];
            if (tid < 64) { s_b1[tid] = gb1[tid]; s_b2[tid] = gb2[tid]; }
            if (tid < 16) s_b3[tid] = gb3[tid];
        }
        // ---- stage u slice (per warp): lane l = sample sbase+l ----
        {
            const float* up = u + (sbase + l) * (NNODES * 16) + node * 16;
            float* inf = (float*)s_in;
            const int p = l >> 1, c = l & 1;
            #pragma unroll
            for (int dd = 0; dd < 16; dd += 4) {
                float4 v4 = *(const float4*)(up + dd);
                inf[(p * IN_STR + 64 + dd + 0) * 2 + c] = v4.x;
                inf[(p * IN_STR + 64 + dd + 1) * 2 + c] = v4.y;
                inf[(p * IN_STR + 64 + dd + 2) * 2 + c] = v4.z;
                inf[(p * IN_STR + 64 + dd + 3) * 2 + c] = v4.w;
            }
        }
        __syncthreads();

        // inner-product block: weights W[wrow+kk][64] (this lane's 2 cols),
        // acts sbuf[p][arow+kk] (u64 sample-pairs), 2 k's per iteration.
        auto mm = [&](const float* W, int wrow, u64* sbuf, int stride, int arow,
                      int kcount) {
            #pragma unroll 1
            for (int kk = 0; kk < kcount; kk += 2) {
                float2 wa = *(const float2*)(W + (wrow + kk) * 64 + 2 * l);
                float2 wb = *(const float2*)(W + (wrow + kk + 1) * 64 + 2 * l);
                const u64 A0 = dup2(wa.x), A1 = dup2(wa.y);
                const u64 B0 = dup2(wb.x), B1 = dup2(wb.y);
                const u64* ab = sbuf + arow + kk;
                #pragma unroll
                for (int p = 0; p < 16; ++p) {
                    ulonglong2 xx = *(const ulonglong2*)(ab + p * stride);
                    acc0[p] = fma2(xx.x, A0, acc0[p]);
                    acc0[p] = fma2(xx.y, B0, acc0[p]);
                    acc1[p] = fma2(xx.x, A1, acc1[p]);
                    acc1[p] = fma2(xx.y, B1, acc1[p]);
                }
            }
        };

        // ---- layer 1 ----
        {
            const u64 d0 = dup2(s_b1[2 * l]), d1 = dup2(s_b1[2 * l + 1]);
            #pragma unroll
            for (int p = 0; p < 16; ++p) { acc0[p] = d0; acc1[p] = d1; }
        }
        if (!root) {
            #pragma unroll 1
            for (int q = 0; q < 4; ++q)
                mm(s_w1, q * 16, s_in, IN_STR, ((node + q) & 3) * 16, 16);
            mm(s_w1, 64, s_in, IN_STR, 64, 16);
        } else {
            mm(s_w1, 0, s_in, IN_STR, 64, 16);
        }
        #pragma unroll
        for (int p = 0; p < 16; ++p) {
            ulonglong2 r; r.x = relu2(acc0[p]); r.y = relu2(acc1[p]);
            *(ulonglong2*)(s_h + p * H_STR + 2 * l) = r;
        }
        __syncwarp();

        // ---- layer 2 ----
        {
            const u64 d0 = dup2(s_b2[2 * l]), d1 = dup2(s_b2[2 * l + 1]);
            #pragma unroll
            for (int p = 0; p < 16; ++p) { acc0[p] = d0; acc1[p] = d1; }
        }
        mm(s_w2, 0, s_h, H_STR, 0, 64);
        __syncwarp();  // everyone finished reading old h
        #pragma unroll
        for (int p = 0; p < 16; ++p) {
            ulonglong2 r; r.x = relu2(acc0[p]); r.y = relu2(acc1[p]);
            *(ulonglong2*)(s_h + p * H_STR + 2 * l) = r;
        }
        __syncwarp();

        // ---- layer 3: lane (q8, g) -> outputs (2q8, 2q8+1), pairs 4g..4g+3 ----
        u64 c0[4], c1[4];
        {
            const u64 d0 = dup2(s_b3[2 * q8]), d1 = dup2(s_b3[2 * q8 + 1]);
            #pragma unroll
            for (int pl = 0; pl < 4; ++pl) { c0[pl] = d0; c1[pl] = d1; }
        }
        #pragma unroll 1
        for (int kk = 0; kk < 64; kk += 2) {
            float2 wa = *(const float2*)(s_w3 + kk * 16 + 2 * q8);
            float2 wb = *(const float2*)(s_w3 + (kk + 1) * 16 + 2 * q8);
            const u64 A0 = dup2(wa.x), A1 = dup2(wa.y);
            const u64 B0 = dup2(wb.x), B1 = dup2(wb.y);
            #pragma unroll
            for (int pl = 0; pl < 4; ++pl) {
                ulonglong2 xx =
                    *(const ulonglong2*)(s_h + (4 * g + pl) * H_STR + kk);
                c0[pl] = fma2(xx.x, A0, c0[pl]);
                c0[pl] = fma2(xx.y, B0, c0[pl]);
                c1[pl] = fma2(xx.x, A1, c1[pl]);
                c1[pl] = fma2(xx.y, B1, c1[pl]);
            }
        }

        // ---- outputs: raw logits to gmem, thresholded bits to parent ring ----
        const int slot = (node & 3) * 16;
        #pragma unroll
        for (int pl = 0; pl < 4; ++pl) {
            const int p = 4 * g + pl;
            const long s0 = sbase + 2 * p;
            float v00, v01, v10, v11;
            unpk(c0[pl], v00, v01);   // output dim 2q8, samples (2p, 2p+1)
            unpk(c1[pl], v10, v11);   // output dim 2q8+1
            float* o0 = out + s0 * (NNODES * 16) + node * 16 + 2 * q8;
            float* o1 = o0 + (NNODES * 16);
            o0[0] = v00; o0[1] = v10;
            o1[0] = v01; o1[1] = v11;
            s_in[p * IN_STR + slot + 2 * q8] =
                pk(v00 > 0.5f ? 1.0f : 0.0f, v01 > 0.5f ? 1.0f : 0.0f);
            s_in[p * IN_STR + slot + 2 * q8 + 1] =
                pk(v10 > 0.5f ? 1.0f : 0.0f, v11 > 0.5f ? 1.0f : 0.0f);
        }
        __syncwarp();
    }
}

extern "C" void kernel_launch(void* const* d_in, const int* in_sizes, int n_in,
                              void* d_out, int out_size) {
    (void)in_sizes; (void)n_in; (void)out_size;
    cudaFuncSetAttribute(ncm_kernel, cudaFuncAttributeMaxDynamicSharedMemorySize,
                         SMEM_BYTES);
    ncm_kernel<<<NBLK, TPB, SMEM_BYTES>>>(
        (const float*)d_in[0],
        (const float*)d_in[1], (const float*)d_in[2],
        (const float*)d_in[3], (const float*)d_in[4],
        (const float*)d_in[5], (const float*)d_in[6],
        (const float*)d_in[7], (const float*)d_in[8],
        (const float*)d_in[9], (const float*)d_in[10],
        (const float*)d_in[11], (const float*)d_in[12],
        (float*)d_out);
}